// round 7
// baseline (speedup 1.0000x reference)
#include <cuda_runtime.h>

#define DD   32
#define HH   128
#define WW   160
#define HWSZ (HH*WW)          // 20480
#define DHW  (DD*HWSZ)        // 655360
#define CIN_ 16
#define COUT_ 32

// ---------------- packed f32x2 helpers (Blackwell FFMA2 path) --------------
typedef unsigned long long u64t;

__device__ __forceinline__ u64t pack2(float a, float b) {
    u64t r;
    asm("mov.b64 %0, {%1, %2};" : "=l"(r) : "f"(a), "f"(b));
    return r;
}
__device__ __forceinline__ void fma2(u64t& d, u64t a, u64t b) {
    asm("fma.rn.f32x2 %0, %1, %2, %0;" : "+l"(d) : "l"(a), "l"(b));
}
__device__ __forceinline__ float2 unpack2(u64t v) {
    float2 r;
    asm("mov.b64 {%0, %1}, %2;" : "=f"(r.x), "=f"(r.y) : "l"(v));
    return r;
}

// ---------------- scratch (allocation-free: device globals) ----------------
__device__ float g_t1 [COUT_ * DHW];     // deformable conv out (raw, pre-BN1)
__device__ float g_u  [COUT_ * DHW];     // conv3d(w2) out
__device__ float g_id [COUT_ * DHW];     // conv3d(wd) out
__device__ float g_s1sum[COUT_ * DD], g_s1sq[COUT_ * DD];
__device__ float g_s2sum[COUT_], g_s2sq[COUT_], g_sdsum[COUT_], g_sdsq[COUT_];
__device__ float g_a1[COUT_ * DD], g_b1f[COUT_ * DD];
__device__ float g_a2[COUT_], g_b2f[COUT_], g_ad[COUT_], g_bdf[COUT_];
// pre-transposed weights (smem-layout order, coalesced staging)
__device__ float g_w2t[8 * 3456];        // [chunk][(cl*27+t)*32+o]
__device__ float g_wdt[4 * 3456];
__device__ float g_wrt[4608];            // [(c*9+k)*32+o]
__device__ float g_wot[2592];            // [(c*9+k)*18+j]

// ---------------- kernel 0: zero stats ------------------------------------
__global__ void zero_stats_kernel() {
    int i = blockIdx.x * blockDim.x + threadIdx.x;
    if (i < COUT_ * DD) { g_s1sum[i] = 0.f; g_s1sq[i] = 0.f; }
    if (i < COUT_)      { g_s2sum[i] = 0.f; g_s2sq[i] = 0.f;
                          g_sdsum[i] = 0.f; g_sdsq[i] = 0.f; }
}

// ---------------- kernel 0b: weight pre-transpose --------------------------
__global__ void prep_weights_kernel(const float* __restrict__ w2,
                                    const float* __restrict__ wd,
                                    const float* __restrict__ w_reg,
                                    const float* __restrict__ w_off) {
    int i = blockIdx.x * blockDim.x + threadIdx.x;
    if (i < 27648) {                       // w2: r = c*27+t (c=0..31)
        int o = i & 31, r = i >> 5;
        g_w2t[i] = w2[(o * 32 + r / 27) * 27 + r % 27];
    }
    if (i < 13824) {                       // wd: c=0..15
        int o = i & 31, r = i >> 5;
        g_wdt[i] = wd[(o * 16 + r / 27) * 27 + r % 27];
    }
    if (i < 4608) {
        int o = i & 31, ck = i >> 5;
        g_wrt[i] = w_reg[o * 144 + ck];
    }
    if (i < 2592) {
        int j = i % 18, ck = i / 18;
        g_wot[i] = w_off[j * 144 + ck];
    }
}

// ---------------- kernel 1: fused offset conv + deformable conv ------------
// block (32,8), grid (5,16,32); offsets computed in-register, parked in smem.
__global__ void __launch_bounds__(256) deform_kernel(const float* __restrict__ x,
                                                     const float* __restrict__ f) {
    extern __shared__ float sm[];
    float* sf   = sm;              // 16*400 = 6400  (f tile, stride 40, +3 skew)
    float* swo  = sm + 6400;       // 2592
    float* swr  = sm + 8992;       // 4608
    float* soff = sm + 13600;      // 18*256 = 4608
    float* ssum = sm + 18208;      // 32
    float* ssq  = sm + 18240;      // 32   (total 18272 floats = 73 KB)

    const int tid  = threadIdx.y * 32 + threadIdx.x;
    const int warp = tid >> 5, lane = tid & 31;
    const int d = blockIdx.z, h0 = blockIdx.y * 8, w0 = blockIdx.x * 32;
    const int ty = threadIdx.y, tx = threadIdx.x;

    for (int i = tid; i < 648;  i += 256) ((float4*)swo)[i] = ((const float4*)g_wot)[i];
    for (int i = tid; i < 1152; i += 256) ((float4*)swr)[i] = ((const float4*)g_wrt)[i];
    if (tid < 32) { ssum[tid] = 0.f; ssq[tid] = 0.f; }

    // stage f tile: 16 planes x 10 rows x cols[-1..32]
#pragma unroll
    for (int c = 0; c < 16; c++) {
        const float* base = f + (size_t)c * DHW + d * HWSZ;
        for (int r = warp; r < 10; r += 8) {
            int hh = h0 + r - 1;
            bool hok = (hh >= 0) && (hh < HH);
            const float* rowp = base + hh * WW;
            float* dst = sf + c * 400 + r * 40 + 3;
            if (lane < 8) {
                float4 v = make_float4(0.f, 0.f, 0.f, 0.f);
                if (hok) v = *(const float4*)(rowp + w0 + lane * 4);
                *(float4*)(dst + 1 + lane * 4) = v;
            } else if (lane == 8) {
                dst[0]  = (hok && w0 > 0)       ? rowp[w0 - 1]  : 0.f;
            } else if (lane == 9) {
                dst[33] = (hok && w0 + 32 < WW) ? rowp[w0 + 32] : 0.f;
            }
        }
    }
    __syncthreads();

    // ---- phase 1: offset conv (18 outputs per pixel), clip, park in smem
    {
        u64t off2[9];
#pragma unroll
        for (int j = 0; j < 9; j++) off2[j] = 0ull;
        for (int c = 0; c < 16; c++) {
#pragma unroll
            for (int ky = 0; ky < 3; ky++)
#pragma unroll
            for (int kx = 0; kx < 3; kx++) {
                float s = sf[c * 400 + (ty + ky) * 40 + 3 + tx + kx];
                u64t s2 = pack2(s, s);
                const u64t* wp = (const u64t*)&swo[(c * 9 + ky * 3 + kx) * 18];
#pragma unroll
                for (int j = 0; j < 9; j++) fma2(off2[j], s2, wp[j]);
            }
        }
#pragma unroll
        for (int j = 0; j < 9; j++) {
            float2 p = unpack2(off2[j]);
            soff[(2 * j    ) * 256 + tid] = fminf(1.f, fmaxf(-1.f, p.x));
            soff[(2 * j + 1) * 256 + tid] = fminf(1.f, fmaxf(-1.f, p.y));
        }
    }
    // no barrier needed: each thread reads only its own soff slots

    // ---- phase 2: deformable sample + einsum
    const int h = h0 + ty, w = w0 + tx;
    const int pix = d * HWSZ + h * WW + w;
    const float* xd = x + d * HWSZ;

    u64t acc2[16];
#pragma unroll
    for (int j = 0; j < 16; j++) acc2[j] = 0ull;

    for (int k = 0; k < 9; k++) {
        float dy = soff[(2 * k    ) * 256 + tid];
        float dx = soff[(2 * k + 1) * 256 + tid];
        float py = (float)(h - 1 + k / 3) + dy;
        float px = (float)(w - 1 + k % 3) + dx;
        float y0f = floorf(py), x0f = floorf(px);
        float wy = py - y0f, wx = px - x0f;
        int y0 = (int)y0f, x0 = (int)x0f, y1 = y0 + 1, x1 = x0 + 1;
        float my0 = (y0 >= 0 && y0 < HH) ? 1.f : 0.f;
        float my1 = (y1 >= 0 && y1 < HH) ? 1.f : 0.f;
        float mx0 = (x0 >= 0 && x0 < WW) ? 1.f : 0.f;
        float mx1 = (x1 >= 0 && x1 < WW) ? 1.f : 0.f;
        float w00 = (1.f - wy) * (1.f - wx) * my0 * mx0;
        float w01 = (1.f - wy) * wx         * my0 * mx1;
        float w10 = wy         * (1.f - wx) * my1 * mx0;
        float w11 = wy         * wx         * my1 * mx1;
        int y0c = min(max(y0, 0), HH - 1), y1c = min(max(y1, 0), HH - 1);
        int x0c = min(max(x0, 0), WW - 1), x1c = min(max(x1, 0), WW - 1);
        int o00 = y0c * WW + x0c, o01 = y0c * WW + x1c;
        int o10 = y1c * WW + x0c, o11 = y1c * WW + x1c;

#pragma unroll 4
        for (int c = 0; c < 16; c++) {
            const float* xc = xd + c * DHW;
            float v = w00 * __ldg(xc + o00) + w01 * __ldg(xc + o01)
                    + w10 * __ldg(xc + o10) + w11 * __ldg(xc + o11);
            u64t v2 = pack2(v, v);
            const ulonglong2* wp = (const ulonglong2*)&swr[(c * 9 + k) * 32];
#pragma unroll
            for (int q = 0; q < 8; q++) {
                ulonglong2 t2 = wp[q];
                fma2(acc2[2 * q    ], v2, t2.x);
                fma2(acc2[2 * q + 1], v2, t2.y);
            }
        }
    }

    float av[32];
#pragma unroll
    for (int j = 0; j < 16; j++) {
        float2 p = unpack2(acc2[j]);
        av[2 * j] = p.x; av[2 * j + 1] = p.y;
    }
#pragma unroll
    for (int o = 0; o < 32; o++) g_t1[o * DHW + pix] = av[o];

#pragma unroll
    for (int o = 0; o < 32; o++) {
        float s = av[o], q = av[o] * av[o];
#pragma unroll
        for (int sh = 16; sh > 0; sh >>= 1) {
            s += __shfl_xor_sync(0xffffffffu, s, sh);
            q += __shfl_xor_sync(0xffffffffu, q, sh);
        }
        if (tx == 0) { atomicAdd(&ssum[o], s); atomicAdd(&ssq[o], q); }
    }
    __syncthreads();
    if (ty == 0) {
        atomicAdd(&g_s1sum[tx * DD + d], ssum[tx]);
        atomicAdd(&g_s1sq [tx * DD + d], ssq [tx]);
    }
}

// ---------------- kernel 3: fold BN1 stats into scale/shift ----------------
__global__ void bnstats1_kernel(const float* __restrict__ g1,
                                const float* __restrict__ b1) {
    int i = blockIdx.x * blockDim.x + threadIdx.x;
    if (i < COUT_ * DD) {
        int o = i / DD;
        float n = (float)HWSZ;
        float m = g_s1sum[i] / n;
        float v = g_s1sq[i] / n - m * m;
        float a = g1[o] * rsqrtf(fmaxf(v, 0.f) + 1e-5f);
        g_a1[i] = a;
        g_b1f[i] = b1[o] - m * a;
    }
}

// ---------------- conv3d body, P=2 in y, streamlined staging ---------------
// tile layout: plane p=cl*3+dz (720 floats), row stride 40, +3 skew so
// cols 1..32 are 16B-aligned for float4 stores. cols 1..32 <-> ww=w0..w0+31
// are ALWAYS in-bounds (w0 multiple of 32), only cols 0/33 need bounds.
template <int CI, bool FUSE_BN1>
__device__ __forceinline__ void conv3d_body(const float* __restrict__ in,
                                            const float* __restrict__ gwt,
                                            float* __restrict__ out,
                                            float* gsum, float* gsq) {
    extern __shared__ float sm[];
    float* tile = sm;              // 12*720 = 8640
    float* wsh  = sm + 8640;       // 3456
    float* ssum = sm + 12096;      // 32
    float* ssq  = sm + 12128;      // 32  (total 12160 floats = 48640 B)

    const int tid  = threadIdx.y * 32 + threadIdx.x;
    const int warp = tid >> 5, lane = tid & 31;
    const int d = blockIdx.z, h0 = blockIdx.y * 16, w0 = blockIdx.x * 32;
    if (tid < 32) { ssum[tid] = 0.f; ssq[tid] = 0.f; }

    u64t accA[16], accB[16];
#pragma unroll
    for (int j = 0; j < 16; j++) { accA[j] = 0ull; accB[j] = 0ull; }

    for (int chunk = 0; chunk < CI / 4; chunk++) {
        __syncthreads();
        {   // weights: coalesced float4 memcpy from pre-transposed global
            const float4* src = (const float4*)(gwt + chunk * 3456);
            float4* dst4 = (float4*)wsh;
            for (int i = tid; i < 864; i += 256) dst4[i] = src[i];
        }
        // tile: 12 planes x 18 rows x cols[-1..32]
#pragma unroll
        for (int p = 0; p < 12; p++) {
            const int cl = p / 3, dz = p % 3;
            const int cg = chunk * 4 + cl;
            const int dd = d + dz - 1;
            const bool dok = (dd >= 0) && (dd < DD);
            float aa = 0.f, bb = 0.f;
            if (FUSE_BN1 && dok) { aa = g_a1[cg * DD + dd]; bb = g_b1f[cg * DD + dd]; }
            const float* base = in + (size_t)cg * DHW + dd * HWSZ;
            for (int r = warp; r < 18; r += 8) {
                int hh = h0 + r - 1;
                bool hok = dok && (hh >= 0) && (hh < HH);
                const float* rowp = base + hh * WW;
                float* dst = tile + p * 720 + r * 40 + 3;
                if (lane < 8) {
                    float4 v = make_float4(0.f, 0.f, 0.f, 0.f);
                    if (hok) {
                        v = *(const float4*)(rowp + w0 + lane * 4);
                        if (FUSE_BN1) {
                            v.x = fmaxf(fmaf(v.x, aa, bb), 0.f);
                            v.y = fmaxf(fmaf(v.y, aa, bb), 0.f);
                            v.z = fmaxf(fmaf(v.z, aa, bb), 0.f);
                            v.w = fmaxf(fmaf(v.w, aa, bb), 0.f);
                        }
                    }
                    *(float4*)(dst + 1 + lane * 4) = v;
                } else if (lane == 8) {
                    float v = 0.f;
                    if (hok && w0 > 0) {
                        v = rowp[w0 - 1];
                        if (FUSE_BN1) v = fmaxf(fmaf(v, aa, bb), 0.f);
                    }
                    dst[0] = v;
                } else if (lane == 9) {
                    float v = 0.f;
                    if (hok && w0 + 32 < WW) {
                        v = rowp[w0 + 32];
                        if (FUSE_BN1) v = fmaxf(fmaf(v, aa, bb), 0.f);
                    }
                    dst[33] = v;
                }
            }
        }
        __syncthreads();

#pragma unroll 1
        for (int cl = 0; cl < 4; cl++) {
#pragma unroll
            for (int t = 0; t < 27; t++) {
                int dz = t / 9, ky = (t / 3) % 3, kx = t % 3;
                int base = cl * 2160 + dz * 720 + 3 + threadIdx.x + kx;
                float sA = tile[base + (threadIdx.y + ky) * 40];
                float sB = tile[base + (threadIdx.y + 8 + ky) * 40];
                u64t sA2 = pack2(sA, sA);
                u64t sB2 = pack2(sB, sB);
                const ulonglong2* wp = (const ulonglong2*)&wsh[(cl * 27 + t) * 32];
#pragma unroll
                for (int q = 0; q < 8; q++) {
                    ulonglong2 t2 = wp[q];
                    fma2(accA[2 * q    ], sA2, t2.x);
                    fma2(accA[2 * q + 1], sA2, t2.y);
                    fma2(accB[2 * q    ], sB2, t2.x);
                    fma2(accB[2 * q + 1], sB2, t2.y);
                }
            }
        }
    }

    const int pixA = d * HWSZ + (h0 + threadIdx.y) * WW + (w0 + threadIdx.x);
    const int pixB = pixA + 8 * WW;
#pragma unroll
    for (int o = 0; o < 32; o++) {
        float2 pA = unpack2(accA[o >> 1]);
        float2 pB = unpack2(accB[o >> 1]);
        float vA = (o & 1) ? pA.y : pA.x;
        float vB = (o & 1) ? pB.y : pB.x;
        out[o * DHW + pixA] = vA;
        out[o * DHW + pixB] = vB;
        float s = vA + vB, q = vA * vA + vB * vB;
#pragma unroll
        for (int sh = 16; sh > 0; sh >>= 1) {
            s += __shfl_xor_sync(0xffffffffu, s, sh);
            q += __shfl_xor_sync(0xffffffffu, q, sh);
        }
        if (threadIdx.x == 0) { atomicAdd(&ssum[o], s); atomicAdd(&ssq[o], q); }
    }
    __syncthreads();
    if (threadIdx.y == 0) {
        atomicAdd(&gsum[threadIdx.x], ssum[threadIdx.x]);
        atomicAdd(&gsq [threadIdx.x], ssq [threadIdx.x]);
    }
}

__global__ void __launch_bounds__(256) conv3d_u_kernel() {
    conv3d_body<32, true>(g_t1, g_w2t, g_u, g_s2sum, g_s2sq);
}
__global__ void __launch_bounds__(256) conv3d_id_kernel(const float* __restrict__ x) {
    conv3d_body<16, false>(x, g_wdt, g_id, g_sdsum, g_sdsq);
}

// ---------------- kernel 5: fold BN2 / BNd stats ---------------------------
__global__ void bnstats2_kernel(const float* __restrict__ g2,
                                const float* __restrict__ b2,
                                const float* __restrict__ gd,
                                const float* __restrict__ bd) {
    int i = threadIdx.x;
    float n = (float)DHW;
    if (i < 32) {
        float m = g_s2sum[i] / n;
        float v = g_s2sq[i] / n - m * m;
        float a = g2[i] * rsqrtf(fmaxf(v, 0.f) + 1e-5f);
        g_a2[i] = a; g_b2f[i] = b2[i] - m * a;
    } else if (i < 64) {
        int o = i - 32;
        float m = g_sdsum[o] / n;
        float v = g_sdsq[o] / n - m * m;
        float a = gd[o] * rsqrtf(fmaxf(v, 0.f) + 1e-5f);
        g_ad[o] = a; g_bdf[o] = bd[o] - m * a;
    }
}

// ---------------- kernel 6: out = relu(bn(u) + bn(id)), float4 -------------
__global__ void final_kernel(float* __restrict__ out) {
    int o = blockIdx.z, d = blockIdx.y;
    int base = o * DHW + d * HWSZ + (blockIdx.x * 256 + threadIdx.x) * 4;
    float4 u  = *(const float4*)&g_u[base];
    float4 id = *(const float4*)&g_id[base];
    float a2 = g_a2[o], b2 = g_b2f[o], ad = g_ad[o], bd = g_bdf[o];
    float4 r;
    r.x = fmaxf(fmaf(u.x, a2, b2) + fmaf(id.x, ad, bd), 0.f);
    r.y = fmaxf(fmaf(u.y, a2, b2) + fmaf(id.y, ad, bd), 0.f);
    r.z = fmaxf(fmaf(u.z, a2, b2) + fmaf(id.z, ad, bd), 0.f);
    r.w = fmaxf(fmaf(u.w, a2, b2) + fmaf(id.w, ad, bd), 0.f);
    *(float4*)&out[base] = r;
}

// ---------------------------------------------------------------------------
extern "C" void kernel_launch(void* const* d_in, const int* in_sizes, int n_in,
                              void* d_out, int out_size) {
    const float* x     = (const float*)d_in[0];
    const float* f     = (const float*)d_in[1];
    const float* w_off = (const float*)d_in[2];
    const float* w_reg = (const float*)d_in[3];
    const float* g1    = (const float*)d_in[4];
    const float* b1    = (const float*)d_in[5];
    const float* w2    = (const float*)d_in[6];
    const float* g2    = (const float*)d_in[7];
    const float* b2    = (const float*)d_in[8];
    const float* wd    = (const float*)d_in[9];
    const float* gd    = (const float*)d_in[10];
    const float* bd    = (const float*)d_in[11];
    float* out = (float*)d_out;

    const int smem_deform = 18272 * 4;    // 73088 B
    const int smem_conv   = 12160 * 4;    // 48640 B
    static bool attr_done = false;
    if (!attr_done) {
        cudaFuncSetAttribute(deform_kernel,
            cudaFuncAttributeMaxDynamicSharedMemorySize, smem_deform);
        cudaFuncSetAttribute(conv3d_u_kernel,
            cudaFuncAttributeMaxDynamicSharedMemorySize, smem_conv);
        cudaFuncSetAttribute(conv3d_id_kernel,
            cudaFuncAttributeMaxDynamicSharedMemorySize, smem_conv);
        attr_done = true;
    }

    dim3 blk(32, 8);
    dim3 grd(WW / 32, HH / 8, DD);        // (5,16,32) deform
    dim3 grc(WW / 32, HH / 16, DD);       // (5, 8,32) conv3d (P=2 in y)
    dim3 ew4(HWSZ / 1024, DD, COUT_);     // (20,32,32) final, float4/thread

    zero_stats_kernel<<<9, 256>>>();
    prep_weights_kernel<<<108, 256>>>(w2, wd, w_reg, w_off);
    deform_kernel<<<grd, blk, smem_deform>>>(x, f);
    bnstats1_kernel<<<4, 256>>>(g1, b1);
    conv3d_u_kernel<<<grc, blk, smem_conv>>>();
    conv3d_id_kernel<<<grc, blk, smem_conv>>>(x);
    bnstats2_kernel<<<1, 64>>>(g2, b2, gd, bd);
    final_kernel<<<ew4, 256>>>(out);
}

// round 8
// speedup vs baseline: 1.5568x; 1.5568x over previous
#include <cuda_runtime.h>

#define DD   32
#define HH   128
#define WW   160
#define HWSZ (HH*WW)          // 20480
#define DHW  (DD*HWSZ)        // 655360
#define CIN_ 16
#define COUT_ 32

// ---------------- packed f32x2 helpers (Blackwell FFMA2 path) --------------
typedef unsigned long long u64t;

__device__ __forceinline__ u64t pack2(float a, float b) {
    u64t r;
    asm("mov.b64 %0, {%1, %2};" : "=l"(r) : "f"(a), "f"(b));
    return r;
}
__device__ __forceinline__ void fma2(u64t& d, u64t a, u64t b) {
    asm("fma.rn.f32x2 %0, %1, %2, %0;" : "+l"(d) : "l"(a), "l"(b));
}
__device__ __forceinline__ float2 unpack2(u64t v) {
    float2 r;
    asm("mov.b64 {%0, %1}, %2;" : "=f"(r.x), "=f"(r.y) : "l"(v));
    return r;
}

// ---------------- scratch (allocation-free: device globals) ----------------
__device__ float g_off[18 * DHW];        // clipped offsets, [j][d][h][w]
__device__ float g_t1 [COUT_ * DHW];     // deformable conv out (raw, pre-BN1)
__device__ float g_u  [COUT_ * DHW];     // conv3d(w2) out
__device__ float g_id [COUT_ * DHW];     // conv3d(wd) out
__device__ float g_s1sum[COUT_ * DD], g_s1sq[COUT_ * DD];
__device__ float g_s2sum[COUT_], g_s2sq[COUT_], g_sdsum[COUT_], g_sdsq[COUT_];
__device__ float g_a1[COUT_ * DD], g_b1f[COUT_ * DD];
__device__ float g_a2[COUT_], g_b2f[COUT_], g_ad[COUT_], g_bdf[COUT_];
// pre-transposed weights (exact smem layout -> coalesced float4 staging)
__device__ float g_w2t[8 * 3456];        // [chunk][(cl*27+t)*32 + o]
__device__ float g_wdt[4 * 3456];        // [chunk][(cl*27+t)*32 + o]
__device__ float g_wrt[4608];            // [(c*9+k)*32 + o]
__device__ float g_wot[2592];            // [(c*9+k)*18 + j]

// ---------------- kernel 0: zero the stat accumulators ---------------------
__global__ void zero_stats_kernel() {
    int i = blockIdx.x * blockDim.x + threadIdx.x;
    if (i < COUT_ * DD) { g_s1sum[i] = 0.f; g_s1sq[i] = 0.f; }
    if (i < COUT_)      { g_s2sum[i] = 0.f; g_s2sq[i] = 0.f;
                          g_sdsum[i] = 0.f; g_sdsq[i] = 0.f; }
}

// ---------------- kernel 0b: weight pre-transpose --------------------------
__global__ void prep_weights_kernel(const float* __restrict__ w2,
                                    const float* __restrict__ wd,
                                    const float* __restrict__ w_reg,
                                    const float* __restrict__ w_off) {
    int i = blockIdx.x * blockDim.x + threadIdx.x;
    if (i < 27648) {                       // w2: [(chunk*4+cl)*27+t]x[o]
        int o = i & 31, r = i >> 5;        // r = c*27 + t, c = 0..31
        g_w2t[i] = w2[(o * 32 + r / 27) * 27 + r % 27];
    }
    if (i < 13824) {                       // wd: c = 0..15
        int o = i & 31, r = i >> 5;
        g_wdt[i] = wd[(o * 16 + r / 27) * 27 + r % 27];
    }
    if (i < 4608) {
        int o = i & 31, ck = i >> 5;
        g_wrt[i] = w_reg[o * 144 + ck];
    }
    if (i < 2592) {
        int j = i % 18, ck = i / 18;
        g_wot[i] = w_off[j * 144 + ck];
    }
}

// ---------------- kernel 1: offset conv2d (f -> 18ch, clip [-1,1]) ---------
__global__ void offset_kernel(const float* __restrict__ f) {
    __shared__ float sw[16 * 9 * 18];      // [(c*9+k)*18 + j]
    __shared__ float sf[16 * 10 * 34];     // [c][yy][xx]
    const int tid = threadIdx.y * 32 + threadIdx.x;
    for (int i = tid; i < 648; i += 256)
        ((float4*)sw)[i] = ((const float4*)g_wot)[i];
    const int d = blockIdx.z, h0 = blockIdx.y * 8, w0 = blockIdx.x * 32;
    for (int i = tid; i < 16 * 340; i += 256) {
        int c = i / 340, r = i % 340, yy = r / 34, xx = r % 34;
        int hh = h0 + yy - 1, ww = w0 + xx - 1;
        float v = 0.f;
        if (hh >= 0 && hh < HH && ww >= 0 && ww < WW)
            v = f[c * DHW + d * HWSZ + hh * WW + ww];
        sf[i] = v;
    }
    __syncthreads();

    u64t off2[9];
#pragma unroll
    for (int j = 0; j < 9; j++) off2[j] = 0ull;
    const int ty = threadIdx.y, tx = threadIdx.x;
    for (int c = 0; c < 16; c++) {
#pragma unroll
        for (int ky = 0; ky < 3; ky++)
#pragma unroll
        for (int kx = 0; kx < 3; kx++) {
            float s = sf[c * 340 + (ty + ky) * 34 + (tx + kx)];
            u64t s2 = pack2(s, s);
            const u64t* wp = (const u64t*)&sw[(c * 9 + ky * 3 + kx) * 18];
#pragma unroll
            for (int j = 0; j < 9; j++) fma2(off2[j], s2, wp[j]);
        }
    }
    const int pix = d * HWSZ + (h0 + ty) * WW + (w0 + tx);
#pragma unroll
    for (int j = 0; j < 9; j++) {
        float2 p = unpack2(off2[j]);
        g_off[(2 * j    ) * DHW + pix] = fminf(1.f, fmaxf(-1.f, p.x));
        g_off[(2 * j + 1) * DHW + pix] = fminf(1.f, fmaxf(-1.f, p.y));
    }
}

// ---------------- kernel 2: deformable sample + einsum + BN1 stats ---------
__global__ void deform_kernel(const float* __restrict__ x) {
    __shared__ float swr[16 * 9 * 32];     // [(c*9+k)*32 + o]
    __shared__ float ssum[32], ssq[32];
    const int tid = threadIdx.y * 32 + threadIdx.x;
    for (int i = tid; i < 1152; i += 256)
        ((float4*)swr)[i] = ((const float4*)g_wrt)[i];
    if (threadIdx.y == 0) { ssum[threadIdx.x] = 0.f; ssq[threadIdx.x] = 0.f; }
    __syncthreads();

    const int d = blockIdx.z;
    const int h = blockIdx.y * 8 + threadIdx.y;
    const int w = blockIdx.x * 32 + threadIdx.x;
    const int pix = d * HWSZ + h * WW + w;
    const float* xd = x + d * HWSZ;

    u64t acc2[16];
#pragma unroll
    for (int j = 0; j < 16; j++) acc2[j] = 0ull;

    for (int k = 0; k < 9; k++) {
        float dy = g_off[(2 * k    ) * DHW + pix];
        float dx = g_off[(2 * k + 1) * DHW + pix];
        float py = (float)(h - 1 + k / 3) + dy;
        float px = (float)(w - 1 + k % 3) + dx;
        float y0f = floorf(py), x0f = floorf(px);
        float wy = py - y0f, wx = px - x0f;
        int y0 = (int)y0f, x0 = (int)x0f, y1 = y0 + 1, x1 = x0 + 1;
        float my0 = (y0 >= 0 && y0 < HH) ? 1.f : 0.f;
        float my1 = (y1 >= 0 && y1 < HH) ? 1.f : 0.f;
        float mx0 = (x0 >= 0 && x0 < WW) ? 1.f : 0.f;
        float mx1 = (x1 >= 0 && x1 < WW) ? 1.f : 0.f;
        float w00 = (1.f - wy) * (1.f - wx) * my0 * mx0;
        float w01 = (1.f - wy) * wx         * my0 * mx1;
        float w10 = wy         * (1.f - wx) * my1 * mx0;
        float w11 = wy         * wx         * my1 * mx1;
        int y0c = min(max(y0, 0), HH - 1), y1c = min(max(y1, 0), HH - 1);
        int x0c = min(max(x0, 0), WW - 1), x1c = min(max(x1, 0), WW - 1);
        int o00 = y0c * WW + x0c, o01 = y0c * WW + x1c;
        int o10 = y1c * WW + x0c, o11 = y1c * WW + x1c;

#pragma unroll 4
        for (int c = 0; c < 16; c++) {
            const float* xc = xd + c * DHW;
            float v = w00 * __ldg(xc + o00) + w01 * __ldg(xc + o01)
                    + w10 * __ldg(xc + o10) + w11 * __ldg(xc + o11);
            u64t v2 = pack2(v, v);
            const ulonglong2* wp = (const ulonglong2*)&swr[(c * 9 + k) * 32];
#pragma unroll
            for (int q = 0; q < 8; q++) {
                ulonglong2 t2 = wp[q];
                fma2(acc2[2 * q    ], v2, t2.x);
                fma2(acc2[2 * q + 1], v2, t2.y);
            }
        }
    }

    float av[32];
#pragma unroll
    for (int j = 0; j < 16; j++) {
        float2 p = unpack2(acc2[j]);
        av[2 * j] = p.x; av[2 * j + 1] = p.y;
    }
#pragma unroll
    for (int o = 0; o < 32; o++) g_t1[o * DHW + pix] = av[o];

#pragma unroll
    for (int o = 0; o < 32; o++) {
        float s = av[o], q = av[o] * av[o];
#pragma unroll
        for (int sh = 16; sh > 0; sh >>= 1) {
            s += __shfl_xor_sync(0xffffffffu, s, sh);
            q += __shfl_xor_sync(0xffffffffu, q, sh);
        }
        if (threadIdx.x == 0) { atomicAdd(&ssum[o], s); atomicAdd(&ssq[o], q); }
    }
    __syncthreads();
    if (threadIdx.y == 0) {
        atomicAdd(&g_s1sum[threadIdx.x * DD + d], ssum[threadIdx.x]);
        atomicAdd(&g_s1sq [threadIdx.x * DD + d], ssq [threadIdx.x]);
    }
}

// ---------------- kernel 3: fold BN1 stats into scale/shift ----------------
__global__ void bnstats1_kernel(const float* __restrict__ g1,
                                const float* __restrict__ b1) {
    int i = blockIdx.x * blockDim.x + threadIdx.x;
    if (i < COUT_ * DD) {
        int o = i / DD;
        float n = (float)HWSZ;
        float m = g_s1sum[i] / n;
        float v = g_s1sq[i] / n - m * m;
        float a = g1[o] * rsqrtf(fmaxf(v, 0.f) + 1e-5f);
        g_a1[i] = a;
        g_b1f[i] = b1[o] - m * a;
    }
}

// ---------------- conv3d body, P=2 pixel tiling in y ------------------------
// Block (32,8) computes a 32x16 output tile: thread owns rows ty and ty+8.
// Every weight LDS.128 feeds 2 pixels worth of FFMA2. (R5 structure.)
template <int CI, bool FUSE_BN1>
__device__ __forceinline__ void conv3d_body(const float* __restrict__ in,
                                            const float* __restrict__ gwt,
                                            float* __restrict__ out,
                                            float* gsum, float* gsq) {
    __shared__ float tile[4 * 3 * 18 * 34];   // [cl][dz][yy][xx], yy: h0-1..h0+16
    __shared__ float wsh[4 * 27 * 32];        // [(cl*27+t)*32 + o]
    __shared__ float ssum[32], ssq[32];
    const int tid = threadIdx.y * 32 + threadIdx.x;
    const int d = blockIdx.z, h0 = blockIdx.y * 16, w0 = blockIdx.x * 32;
    if (threadIdx.y == 0) { ssum[threadIdx.x] = 0.f; ssq[threadIdx.x] = 0.f; }

    u64t accA[16], accB[16];
#pragma unroll
    for (int j = 0; j < 16; j++) { accA[j] = 0ull; accB[j] = 0ull; }

    for (int chunk = 0; chunk < CI / 4; chunk++) {
        __syncthreads();
        // stage 4 channels x 3 depth x 18 rows x 34 cols = 7344 floats
        for (int i = tid; i < 7344; i += 256) {
            int cl = i / 1836, r = i % 1836, dz = r / 612;
            int r2 = r % 612, yy = r2 / 34, xx = r2 % 34;
            int dd = d + dz - 1, hh = h0 + yy - 1, ww = w0 + xx - 1;
            float v = 0.f;
            if (dd >= 0 && dd < DD && hh >= 0 && hh < HH && ww >= 0 && ww < WW) {
                int cg = chunk * 4 + cl;
                v = in[cg * DHW + dd * HWSZ + hh * WW + ww];
                if (FUSE_BN1)
                    v = fmaxf(fmaf(v, g_a1[cg * DD + dd], g_b1f[cg * DD + dd]), 0.f);
            }
            tile[i] = v;
        }
        // weights: coalesced float4 copy from pre-transposed global
        {
            const float4* src = (const float4*)(gwt + chunk * 3456);
            for (int i = tid; i < 864; i += 256) ((float4*)wsh)[i] = src[i];
        }
        __syncthreads();

#pragma unroll 1
        for (int cl = 0; cl < 4; cl++) {
#pragma unroll
            for (int t = 0; t < 27; t++) {
                int dz = t / 9, ky = (t / 3) % 3, kx = t % 3;
                int base = cl * 1836 + dz * 612 + threadIdx.x + kx;
                float sA = tile[base + (threadIdx.y + ky) * 34];
                float sB = tile[base + (threadIdx.y + 8 + ky) * 34];
                u64t sA2 = pack2(sA, sA);
                u64t sB2 = pack2(sB, sB);
                const ulonglong2* wp = (const ulonglong2*)&wsh[(cl * 27 + t) * 32];
#pragma unroll
                for (int q = 0; q < 8; q++) {
                    ulonglong2 t2 = wp[q];
                    fma2(accA[2 * q    ], sA2, t2.x);
                    fma2(accA[2 * q + 1], sA2, t2.y);
                    fma2(accB[2 * q    ], sB2, t2.x);
                    fma2(accB[2 * q + 1], sB2, t2.y);
                }
            }
        }
    }

    const int pixA = d * HWSZ + (h0 + threadIdx.y) * WW + (w0 + threadIdx.x);
    const int pixB = pixA + 8 * WW;
#pragma unroll
    for (int o = 0; o < 32; o++) {
        float2 pA = unpack2(accA[o >> 1]);
        float2 pB = unpack2(accB[o >> 1]);
        float vA = (o & 1) ? pA.y : pA.x;
        float vB = (o & 1) ? pB.y : pB.x;
        out[o * DHW + pixA] = vA;
        out[o * DHW + pixB] = vB;
        float s = vA + vB, q = vA * vA + vB * vB;
#pragma unroll
        for (int sh = 16; sh > 0; sh >>= 1) {
            s += __shfl_xor_sync(0xffffffffu, s, sh);
            q += __shfl_xor_sync(0xffffffffu, q, sh);
        }
        if (threadIdx.x == 0) { atomicAdd(&ssum[o], s); atomicAdd(&ssq[o], q); }
    }
    __syncthreads();
    if (threadIdx.y == 0) {
        atomicAdd(&gsum[threadIdx.x], ssum[threadIdx.x]);
        atomicAdd(&gsq [threadIdx.x], ssq [threadIdx.x]);
    }
}

__global__ void __launch_bounds__(256) conv3d_u_kernel() {
    conv3d_body<32, true>(g_t1, g_w2t, g_u, g_s2sum, g_s2sq);
}
__global__ void __launch_bounds__(256) conv3d_id_kernel(const float* __restrict__ x) {
    conv3d_body<16, false>(x, g_wdt, g_id, g_sdsum, g_sdsq);
}

// ---------------- kernel 5: fold BN2 / BNd stats ---------------------------
__global__ void bnstats2_kernel(const float* __restrict__ g2,
                                const float* __restrict__ b2,
                                const float* __restrict__ gd,
                                const float* __restrict__ bd) {
    int i = threadIdx.x;
    float n = (float)DHW;
    if (i < 32) {
        float m = g_s2sum[i] / n;
        float v = g_s2sq[i] / n - m * m;
        float a = g2[i] * rsqrtf(fmaxf(v, 0.f) + 1e-5f);
        g_a2[i] = a; g_b2f[i] = b2[i] - m * a;
    } else if (i < 64) {
        int o = i - 32;
        float m = g_sdsum[o] / n;
        float v = g_sdsq[o] / n - m * m;
        float a = gd[o] * rsqrtf(fmaxf(v, 0.f) + 1e-5f);
        g_ad[o] = a; g_bdf[o] = bd[o] - m * a;
    }
}

// ---------------- kernel 6: out = relu(bn(u) + bn(id)), float4 -------------
__global__ void final_kernel(float* __restrict__ out) {
    int o = blockIdx.z, d = blockIdx.y;
    int base = o * DHW + d * HWSZ + (blockIdx.x * 256 + threadIdx.x) * 4;
    float4 u  = *(const float4*)&g_u[base];
    float4 id = *(const float4*)&g_id[base];
    float a2 = g_a2[o], ad = g_ad[o];
    float bb = g_b2f[o] + g_bdf[o];
    float4 r;
    r.x = fmaxf(fmaf(u.x, a2, fmaf(id.x, ad, bb)), 0.f);
    r.y = fmaxf(fmaf(u.y, a2, fmaf(id.y, ad, bb)), 0.f);
    r.z = fmaxf(fmaf(u.z, a2, fmaf(id.z, ad, bb)), 0.f);
    r.w = fmaxf(fmaf(u.w, a2, fmaf(id.w, ad, bb)), 0.f);
    *(float4*)&out[base] = r;
}

// ---------------------------------------------------------------------------
extern "C" void kernel_launch(void* const* d_in, const int* in_sizes, int n_in,
                              void* d_out, int out_size) {
    const float* x     = (const float*)d_in[0];
    const float* f     = (const float*)d_in[1];
    const float* w_off = (const float*)d_in[2];
    const float* w_reg = (const float*)d_in[3];
    const float* g1    = (const float*)d_in[4];
    const float* b1    = (const float*)d_in[5];
    const float* w2    = (const float*)d_in[6];
    const float* g2    = (const float*)d_in[7];
    const float* b2    = (const float*)d_in[8];
    const float* wd    = (const float*)d_in[9];
    const float* gd    = (const float*)d_in[10];
    const float* bd    = (const float*)d_in[11];
    float* out = (float*)d_out;

    dim3 blk(32, 8);
    dim3 grd(WW / 32, HH / 8, DD);        // (5,16,32) offset/deform
    dim3 grc(WW / 32, HH / 16, DD);       // (5, 8,32) conv3d (P=2 in y)
    dim3 ew4(HWSZ / 1024, DD, COUT_);     // (20,32,32) final, float4/thread

    zero_stats_kernel<<<9, 256>>>();
    prep_weights_kernel<<<108, 256>>>(w2, wd, w_reg, w_off);
    offset_kernel<<<grd, blk>>>(f);
    deform_kernel<<<grd, blk>>>(x);
    bnstats1_kernel<<<4, 256>>>(g1, b1);
    conv3d_u_kernel<<<grc, blk>>>();      // BN1+ReLU fused into tile load
    conv3d_id_kernel<<<grc, blk>>>(x);
    bnstats2_kernel<<<1, 64>>>(g2, b2, gd, bd);
    final_kernel<<<ew4, 256>>>(out);
}